// round 9
// baseline (speedup 1.0000x reference)
#include <cuda_runtime.h>
#include <cuda_bf16.h>
#include <cstdint>

// NetG: encoder GRU -> +noise -> decoder GRU -> FC head.
// mma.sync.m16n8k16 bf16 x3-split GEMM. R9: per-warp barrier poll +
// warp-private A staging (each warp stages exactly the A region it
// ldmatrix-reads) -> only 2 CTA-wide __syncthreads per step.

#define TSZ 256
#define HSZ 256
#define BSZ 512
#define NCTA 128
#define NTHR 256

// smem byte offsets
#define A_HI 0                // 64 x 512B swizzled bf16 (Ah)
#define A_LO 32768            // Al
#define CBUF 65536            // float [m stride 212][kw stride 52][n 48]
#define WIHB 119808           // 48 x float4 {w0,w1,w2,bih}
#define BHHO 120576           // 48 floats bhh
#define WFCO 120768           // 48 floats wfc (3 x 16)
#define SMEM_BYTES 120960

__device__ __nv_bfloat16 g_hbf[2][2][BSZ * HSZ];  // [hi/lo][buf][b*256+j]
__device__ float g_yp[2][NCTA][64][4];            // head partials
__device__ unsigned g_cnt[8][32];                 // [bb][pad] monotonic counter

__device__ __forceinline__ uint32_t smem_u32(const void* p) {
    uint32_t a;
    asm("{ .reg .u64 t; cvta.to.shared.u64 t, %1; cvt.u32.u64 %0, t; }"
        : "=r"(a) : "l"(p));
    return a;
}
__device__ __forceinline__ void ldm4(uint32_t* r, uint32_t addr) {
    asm volatile("ldmatrix.sync.aligned.m8n8.x4.shared.b16 {%0,%1,%2,%3}, [%4];"
        : "=r"(r[0]), "=r"(r[1]), "=r"(r[2]), "=r"(r[3]) : "r"(addr));
}
__device__ __forceinline__ void mma16816(float* c, const uint32_t* a,
                                         uint32_t b0, uint32_t b1) {
    asm volatile(
        "mma.sync.aligned.m16n8k16.row.col.f32.bf16.bf16.f32 "
        "{%0,%1,%2,%3}, {%4,%5,%6,%7}, {%8,%9}, {%0,%1,%2,%3};"
        : "+f"(c[0]), "+f"(c[1]), "+f"(c[2]), "+f"(c[3])
        : "r"(a[0]), "r"(a[1]), "r"(a[2]), "r"(a[3]), "r"(b0), "r"(b1));
}
__device__ __forceinline__ void arrive(unsigned* cnt) {
    asm volatile("red.add.release.gpu.u32 [%0], 1;" :: "l"(cnt) : "memory");
}
__device__ __forceinline__ void wait_ge(const unsigned* cnt, unsigned target) {
    unsigned v;
    do {
        asm volatile("ld.acquire.gpu.u32 %0, [%1];" : "=r"(v) : "l"(cnt) : "memory");
    } while ((int)(v - target) < 0);
}
__device__ __forceinline__ float sigf(float x) {
    return __fdividef(1.0f, 1.0f + __expf(-x));
}
__device__ __forceinline__ float tanhf_(float x) {
    return 1.0f - __fdividef(2.0f, __expf(2.0f * x) + 1.0f);
}

// Build this warp's B fragments (weights) in registers, split hi/lo bf16.
__device__ __forceinline__ void stage_Bregs(
    const float* __restrict__ W, uint32_t Bh[6][4][2], uint32_t Bl[6][4][2],
    int ib, int kw, int lane)
{
    const int nr = lane >> 2, kc = (lane & 3) * 2;
    #pragma unroll
    for (int nt = 0; nt < 6; ++nt) {
        int n = nt * 8 + nr;
        int g = n >> 4, c = n & 15;
        const float* row = W + (g * HSZ + ib * 16 + c) * HSZ;
        #pragma unroll
        for (int kt = 0; kt < 4; ++kt) {
            #pragma unroll
            for (int rg = 0; rg < 2; ++rg) {
                int kk = kw * 64 + kt * 16 + rg * 8 + kc;
                float2 w = *(const float2*)(row + kk);
                __nv_bfloat16 h0 = __float2bfloat16(w.x);
                __nv_bfloat16 h1 = __float2bfloat16(w.y);
                __nv_bfloat16 l0 = __float2bfloat16(w.x - __bfloat162float(h0));
                __nv_bfloat16 l1 = __float2bfloat16(w.y - __bfloat162float(h1));
                Bh[nt][kt][rg] = (uint32_t)__bfloat16_as_ushort(h0)
                               | ((uint32_t)__bfloat16_as_ushort(h1) << 16);
                Bl[nt][kt][rg] = (uint32_t)__bfloat16_as_ushort(l0)
                               | ((uint32_t)__bfloat16_as_ushort(l1) << 16);
            }
        }
    }
}

extern "C" __global__ void __launch_bounds__(NTHR, 1)
netg_mma(const float* __restrict__ X_p, const float* __restrict__ X_f,
         const float* __restrict__ noise,
         const float* __restrict__ Wih_e, const float* __restrict__ Whh_e,
         const float* __restrict__ bih_e, const float* __restrict__ bhh_e,
         const float* __restrict__ Wih_d, const float* __restrict__ Whh_d,
         const float* __restrict__ bih_d, const float* __restrict__ bhh_d,
         const float* __restrict__ Wfc,   const float* __restrict__ bfc,
         float* __restrict__ out)
{
    extern __shared__ char smc[];
    const uint32_t smb = smem_u32(smc);
    const int tid = threadIdx.x, lane = tid & 31, wid = tid >> 5;
    const int bb = blockIdx.x >> 4, ib = blockIdx.x & 15;
    const int mw = wid & 1, kw = wid >> 1;

    float4* wihb_s = (float4*)(smc + WIHB);
    float*  bhh_s  = (float*)(smc + BHHO);
    float*  wfc_s  = (float*)(smc + WFCO);
    unsigned* cnt  = &g_cnt[bb][0];

    // ---- weights into registers / params into SMEM (encoder phase) ----
    uint32_t Bh[6][4][2], Bl[6][4][2];
    stage_Bregs(Whh_e, Bh, Bl, ib, kw, lane);
    if (tid < 48) {
        int g = tid >> 4, c = tid & 15;
        int row = g * HSZ + ib * 16 + c;
        wihb_s[tid] = make_float4(Wih_e[row * 3], Wih_e[row * 3 + 1],
                                  Wih_e[row * 3 + 2], bih_e[row]);
        bhh_s[tid] = bhh_e[row];
        wfc_s[tid] = Wfc[g * HSZ + ib * 16 + c];
    }

    // epilogue mapping: m = tid>>2 (batch local), iq = tid&3 (4 hid each)
    const int m_e = tid >> 2, iq = tid & 3;
    const int bg = bb * 64 + m_e;

    // zero h buffer 0 (production index 0)
    {
        uint2 z = make_uint2(0u, 0u);
        *(uint2*)(&g_hbf[0][0][bg * HSZ + ib * 16 + iq * 4]) = z;
        *(uint2*)(&g_hbf[1][0][bg * HSZ + ib * 16 + iq * 4]) = z;
    }
    float hprev[4] = {0.f, 0.f, 0.f, 0.f};
    __syncthreads();
    if (tid == 0) arrive(cnt);   // init arrival: buffer 0 published

    // ldmatrix per-lane address bases (warp-private A region: rows
    // [mw*32, mw*32+32), k-quarter kw)
    const int lgrp = lane >> 3, lrow = lane & 7;
    const int r0 = mw * 32 + ((lgrp & 1) << 3) + lrow;
    const int segoff = lgrp >> 1;
    const uint32_t rbh0 = smb + A_HI + r0 * 512;
    const uint32_t rbh1 = rbh0 + 16 * 512;
    const uint32_t rbl0 = smb + A_LO + r0 * 512;
    const uint32_t rbl1 = rbl0 + 16 * 512;

    // self-staging per-lane source/dest precompute:
    // 512 16B-chunks per warp: idx = lane + it*32;
    // p = idx>>8, rem = idx&255, row = rem>>3 (0..31), s8 = rem&7
    for (int t = 0; t < 2 * TSZ; ++t) {
        const bool enc = t < TSZ;
        const int tt = enc ? t : t - TSZ;

        // ---- per-warp entry: all 16 producers of this group reached index t ----
        if (lane == 0) wait_ge(cnt, 16u * (unsigned)(t + 1));
        __syncwarp();

        if (t == TSZ) {   // switch to decoder weights
            stage_Bregs(Whh_d, Bh, Bl, ib, kw, lane);
            if (tid < 48) {
                int g = tid >> 4, c = tid & 15;
                int row = g * HSZ + ib * 16 + c;
                wihb_s[tid] = make_float4(Wih_d[row * 3], Wih_d[row * 3 + 1],
                                          Wih_d[row * 3 + 2], bih_d[row]);
                bhh_s[tid] = bhh_d[row];
            }
        }

        // x_t prefetch (latency hides under staging)
        float x0 = 0.f, x1 = 0.f, x2 = 0.f;
        if (enc) {
            const float* xp = X_p + bg * (TSZ * 3) + tt * 3;
            x0 = xp[0]; x1 = xp[1]; x2 = xp[2];
        } else if (tt > 0) {
            const float* xp = X_f + bg * (TSZ * 3) + (tt - 1) * 3;
            x0 = xp[0]; x1 = xp[1]; x2 = xp[2];
        }

        // ---- warp-private A staging: own 32 rows x own k-quarter, hi+lo ----
        {
            const __nv_bfloat16* s_hi = g_hbf[0][t & 1]
                + (bb * 64 + mw * 32) * HSZ + kw * 64;
            const __nv_bfloat16* s_lo = g_hbf[1][t & 1]
                + (bb * 64 + mw * 32) * HSZ + kw * 64;
            #pragma unroll
            for (int it = 0; it < 16; ++it) {
                int idx = lane + it * 32;
                int p = idx >> 8, rem = idx & 255;
                int row = rem >> 3, s8 = rem & 7;
                const __nv_bfloat16* src = (p ? s_lo : s_hi) + row * HSZ + s8 * 8;
                uint32_t S = (uint32_t)(kw * 8 + s8);
                uint32_t dst = smb + (p ? A_LO : A_HI)
                             + (uint32_t)(mw * 32 + row) * 512
                             + ((S ^ (uint32_t)(row & 7)) << 4);
                *(uint4*)(smc + (dst - smb)) = *(const uint4*)src;
            }
        }
        __syncwarp();

        // ---- tensor-core GEMM: C[m 0..63][n 0..47] partial over K-quarter ----
        float c[2][6][4];
        #pragma unroll
        for (int a = 0; a < 2; ++a)
            #pragma unroll
            for (int b2 = 0; b2 < 6; ++b2)
                #pragma unroll
                for (int d2 = 0; d2 < 4; ++d2) c[a][b2][d2] = 0.f;

        #pragma unroll
        for (int kt = 0; kt < 4; ++kt) {
            int seg = kw * 8 + kt * 2 + segoff;
            uint32_t so = (uint32_t)((seg ^ lrow) << 4);
            uint32_t ah0[4], ah1[4], al0[4], al1[4];
            ldm4(ah0, rbh0 + so);
            ldm4(ah1, rbh1 + so);
            ldm4(al0, rbl0 + so);
            ldm4(al1, rbl1 + so);
            #pragma unroll
            for (int nt = 0; nt < 6; ++nt) {
                mma16816(c[0][nt], ah0, Bh[nt][kt][0], Bh[nt][kt][1]);
                mma16816(c[1][nt], ah1, Bh[nt][kt][0], Bh[nt][kt][1]);
                mma16816(c[0][nt], al0, Bh[nt][kt][0], Bh[nt][kt][1]);
                mma16816(c[1][nt], al1, Bh[nt][kt][0], Bh[nt][kt][1]);
                mma16816(c[0][nt], ah0, Bl[nt][kt][0], Bl[nt][kt][1]);
                mma16816(c[1][nt], ah1, Bl[nt][kt][0], Bl[nt][kt][1]);
            }
        }

        // store K-partials to SMEM
        {
            float* cb = (float*)(smc + CBUF);
            int rr = lane >> 2, cc = (lane & 3) * 2;
            #pragma unroll
            for (int mt = 0; mt < 2; ++mt)
                #pragma unroll
                for (int nt = 0; nt < 6; ++nt) {
                    int mm = mw * 32 + mt * 16 + rr;
                    int nn = nt * 8 + cc;
                    float* p0 = cb + mm * 212 + kw * 52 + nn;
                    *(float2*)p0 = make_float2(c[mt][nt][0], c[mt][nt][1]);
                    *(float2*)(p0 + 8 * 212) = make_float2(c[mt][nt][2], c[mt][nt][3]);
                }
        }

        // distributed head reduce (inputs ready since barrier; overlaps MMA tail)
        if (t > TSZ && tid < 12) {
            int bl = ib * 4 + tid / 3, d = tid - (tid / 3) * 3;
            float s2 = bfc[d];
            #pragma unroll
            for (int p = 0; p < 16; ++p)
                s2 += g_yp[(t & 1) ^ 1][bb * 16 + p][bl][d];
            out[((bb * 64 + bl) * TSZ + (tt - 1)) * 3 + d] = s2;
        }
        __syncthreads();

        // ---- epilogue: reduce 4 K-partials, gates, h update ----
        const float* cb = (float*)(smc + CBUF) + m_e * 212 + iq * 4;
        float4 sR = *(const float4*)(cb);
        float4 sZ = *(const float4*)(cb + 16);
        float4 sN = *(const float4*)(cb + 32);
        #pragma unroll
        for (int k2 = 1; k2 < 4; ++k2) {
            const float* p = cb + k2 * 52;
            float4 a = *(const float4*)(p);
            float4 b2 = *(const float4*)(p + 16);
            float4 d2 = *(const float4*)(p + 32);
            sR.x += a.x;  sR.y += a.y;  sR.z += a.z;  sR.w += a.w;
            sZ.x += b2.x; sZ.y += b2.y; sZ.z += b2.z; sZ.w += b2.w;
            sN.x += d2.x; sN.y += d2.y; sN.z += d2.z; sN.w += d2.w;
        }
        float sRa[4] = {sR.x, sR.y, sR.z, sR.w};
        float sZa[4] = {sZ.x, sZ.y, sZ.z, sZ.w};
        float sNa[4] = {sN.x, sN.y, sN.z, sN.w};
        float4 bR4 = *(const float4*)(bhh_s + iq * 4);
        float4 bZ4 = *(const float4*)(bhh_s + 16 + iq * 4);
        float4 bN4 = *(const float4*)(bhh_s + 32 + iq * 4);
        float bRa[4] = {bR4.x, bR4.y, bR4.z, bR4.w};
        float bZa[4] = {bZ4.x, bZ4.y, bZ4.z, bZ4.w};
        float bNa[4] = {bN4.x, bN4.y, bN4.z, bN4.w};

        const bool addn = (t == TSZ - 1);
        float h4[4];
        #pragma unroll
        for (int q = 0; q < 4; ++q) {
            int i = iq * 4 + q;
            float4 wR = wihb_s[i], wZ = wihb_s[16 + i], wN = wihb_s[32 + i];
            float xr = wR.w + wR.x * x0 + wR.y * x1 + wR.z * x2;
            float xz = wZ.w + wZ.x * x0 + wZ.y * x1 + wZ.z * x2;
            float xn = wN.w + wN.x * x0 + wN.y * x1 + wN.z * x2;
            float r = sigf(xr + sRa[q] + bRa[q]);
            float z = sigf(xz + sZa[q] + bZa[q]);
            float n = tanhf_(xn + r * (sNa[q] + bNa[q]));
            float h = n + z * (hprev[q] - n);
            if (addn) h += noise[bg * HSZ + ib * 16 + iq * 4 + q];
            hprev[q] = h;
            h4[q] = h;
        }

        // write split h for next step (production index t+1, buf (t+1)&1)
        {
            __nv_bfloat16 h0 = __float2bfloat16(h4[0]);
            __nv_bfloat16 h1 = __float2bfloat16(h4[1]);
            __nv_bfloat16 h2 = __float2bfloat16(h4[2]);
            __nv_bfloat16 h3 = __float2bfloat16(h4[3]);
            __nv_bfloat16 l0 = __float2bfloat16(h4[0] - __bfloat162float(h0));
            __nv_bfloat16 l1 = __float2bfloat16(h4[1] - __bfloat162float(h1));
            __nv_bfloat16 l2 = __float2bfloat16(h4[2] - __bfloat162float(h2));
            __nv_bfloat16 l3 = __float2bfloat16(h4[3] - __bfloat162float(h3));
            uint32_t hiA = (uint32_t)__bfloat16_as_ushort(h0)
                         | ((uint32_t)__bfloat16_as_ushort(h1) << 16);
            uint32_t hiB = (uint32_t)__bfloat16_as_ushort(h2)
                         | ((uint32_t)__bfloat16_as_ushort(h3) << 16);
            uint32_t loA = (uint32_t)__bfloat16_as_ushort(l0)
                         | ((uint32_t)__bfloat16_as_ushort(l1) << 16);
            uint32_t loB = (uint32_t)__bfloat16_as_ushort(l2)
                         | ((uint32_t)__bfloat16_as_ushort(l3) << 16);
            int off = bg * HSZ + ib * 16 + iq * 4;
            *(uint2*)(&g_hbf[0][(t + 1) & 1][off]) = make_uint2(hiA, hiB);
            *(uint2*)(&g_hbf[1][(t + 1) & 1][off]) = make_uint2(loA, loB);
        }

        // fused FC head partial (decoder)
        if (!enc) {
            float4 w0 = *(const float4*)(wfc_s + iq * 4);
            float4 w1 = *(const float4*)(wfc_s + 16 + iq * 4);
            float4 w2 = *(const float4*)(wfc_s + 32 + iq * 4);
            float y0 = h4[0] * w0.x + h4[1] * w0.y + h4[2] * w0.z + h4[3] * w0.w;
            float y1 = h4[0] * w1.x + h4[1] * w1.y + h4[2] * w1.z + h4[3] * w1.w;
            float y2 = h4[0] * w2.x + h4[1] * w2.y + h4[2] * w2.z + h4[3] * w2.w;
            y0 += __shfl_xor_sync(0xffffffffu, y0, 1);
            y0 += __shfl_xor_sync(0xffffffffu, y0, 2);
            y1 += __shfl_xor_sync(0xffffffffu, y1, 1);
            y1 += __shfl_xor_sync(0xffffffffu, y1, 2);
            y2 += __shfl_xor_sync(0xffffffffu, y2, 1);
            y2 += __shfl_xor_sync(0xffffffffu, y2, 2);
            if (iq == 0)
                *(float4*)(&g_yp[t & 1][blockIdx.x][m_e][0]) =
                    make_float4(y0, y1, y2, 0.f);
        }

        // publish production index t+1
        __syncthreads();
        if (tid == 0) arrive(cnt);
    }

    // final head reduction for tstep = 255 (partials at t=511, buf par=1)
    if (tid == 0) wait_ge(cnt, 16u * 513u);
    __syncthreads();
    if (tid < 12) {
        int bl = ib * 4 + tid / 3, d = tid - (tid / 3) * 3;
        float s2 = bfc[d];
        #pragma unroll
        for (int p = 0; p < 16; ++p)
            s2 += g_yp[1][bb * 16 + p][bl][d];
        out[((bb * 64 + bl) * TSZ + (TSZ - 1)) * 3 + d] = s2;
    }
    __syncthreads();
    if (tid == 0) arrive(cnt);

    // counter reset for graph replay: ib==0 waits for all final arrivals,
    // then stores 0 (no CTA reads the counter after its last arrival).
    if (ib == 0 && tid == 0) {
        wait_ge(cnt, 16u * 514u);
        asm volatile("st.release.gpu.u32 [%0], %1;" :: "l"(cnt), "r"(0u) : "memory");
    }
}

extern "C" void kernel_launch(void* const* d_in, const int* in_sizes, int n_in,
                              void* d_out, int out_size) {
    const float* X_p   = (const float*)d_in[0];
    const float* X_f   = (const float*)d_in[1];
    const float* noise = (const float*)d_in[2];
    const float* Wih_e = (const float*)d_in[3];
    const float* Whh_e = (const float*)d_in[4];
    const float* bih_e = (const float*)d_in[5];
    const float* bhh_e = (const float*)d_in[6];
    const float* Wih_d = (const float*)d_in[7];
    const float* Whh_d = (const float*)d_in[8];
    const float* bih_d = (const float*)d_in[9];
    const float* bhh_d = (const float*)d_in[10];
    const float* Wfc   = (const float*)d_in[11];
    const float* bfc   = (const float*)d_in[12];
    float* out = (float*)d_out;

    cudaFuncSetAttribute(netg_mma, cudaFuncAttributeMaxDynamicSharedMemorySize,
                         SMEM_BYTES);
    netg_mma<<<NCTA, NTHR, SMEM_BYTES>>>(
        X_p, X_f, noise, Wih_e, Whh_e, bih_e, bhh_e,
        Wih_d, Whh_d, bih_d, bhh_d, Wfc, bfc, out);
}

// round 10
// speedup vs baseline: 1.1896x; 1.1896x over previous
#include <cuda_runtime.h>
#include <cuda_bf16.h>
#include <cstdint>

// NetG: encoder GRU -> +noise -> decoder GRU -> FC head.
// mma.sync.m16n8k16 bf16 x3-split GEMM (R8 engine/structure).
// R10: re-tile as 16 batch-groups(32) x 8 hidden-blocks(N=96):
// half the A staging, half the barrier width; MMA work/regs unchanged.

#define TSZ 256
#define HSZ 256
#define BSZ 512
#define NCTA 128
#define NTHR 256

// smem byte offsets
#define A_HI 0                // 32 x 512B swizzled bf16 (Ah)
#define A_LO 16384            // Al
#define CBUF 32768            // float [m stride 404][kw stride 100][n 96]
#define WIHB 84480            // 96 x float4 {w0,w1,w2,bih}
#define BHHO 86016            // 96 floats bhh
#define WFCO 86400            // 96 floats wfc (3 x 32)
#define SMEM_BYTES 86784

__device__ __nv_bfloat16 g_hbf[2][2][BSZ * HSZ];  // [hi/lo][buf][b*256+j]
__device__ float g_yp[2][NCTA][32][4];            // head partials
__device__ unsigned g_cnt[16][32];                // [bb][pad] monotonic counter

__device__ __forceinline__ uint32_t smem_u32(const void* p) {
    uint32_t a;
    asm("{ .reg .u64 t; cvta.to.shared.u64 t, %1; cvt.u32.u64 %0, t; }"
        : "=r"(a) : "l"(p));
    return a;
}
__device__ __forceinline__ void ldm4(uint32_t* r, uint32_t addr) {
    asm volatile("ldmatrix.sync.aligned.m8n8.x4.shared.b16 {%0,%1,%2,%3}, [%4];"
        : "=r"(r[0]), "=r"(r[1]), "=r"(r[2]), "=r"(r[3]) : "r"(addr));
}
__device__ __forceinline__ void mma16816(float* c, const uint32_t* a,
                                         uint32_t b0, uint32_t b1) {
    asm volatile(
        "mma.sync.aligned.m16n8k16.row.col.f32.bf16.bf16.f32 "
        "{%0,%1,%2,%3}, {%4,%5,%6,%7}, {%8,%9}, {%0,%1,%2,%3};"
        : "+f"(c[0]), "+f"(c[1]), "+f"(c[2]), "+f"(c[3])
        : "r"(a[0]), "r"(a[1]), "r"(a[2]), "r"(a[3]), "r"(b0), "r"(b1));
}
__device__ __forceinline__ void arrive(unsigned* cnt) {
    asm volatile("red.add.release.gpu.u32 [%0], 1;" :: "l"(cnt) : "memory");
}
__device__ __forceinline__ void wait_ge(const unsigned* cnt, unsigned target) {
    unsigned v;
    do {
        asm volatile("ld.acquire.gpu.u32 %0, [%1];" : "=r"(v) : "l"(cnt) : "memory");
    } while ((int)(v - target) < 0);
}
__device__ __forceinline__ float sigf(float x) {
    return __fdividef(1.0f, 1.0f + __expf(-x));
}
__device__ __forceinline__ float tanhf_(float x) {
    return 1.0f - __fdividef(2.0f, __expf(2.0f * x) + 1.0f);
}

// Build this warp's B fragments (weights) in registers, split hi/lo bf16.
// Warp covers n-rows [nw*48, nw*48+48), k-quarter [kw*64, kw*64+64).
__device__ __forceinline__ void stage_Bregs(
    const float* __restrict__ W, uint32_t Bh[6][4][2], uint32_t Bl[6][4][2],
    int ib, int nw, int kw, int lane)
{
    const int nr = lane >> 2, kc = (lane & 3) * 2;
    #pragma unroll
    for (int nt = 0; nt < 6; ++nt) {
        int n = nw * 48 + nt * 8 + nr;
        int g = n >> 5, c = n & 31;
        const float* row = W + (g * HSZ + ib * 32 + c) * HSZ;
        #pragma unroll
        for (int kt = 0; kt < 4; ++kt) {
            #pragma unroll
            for (int rg = 0; rg < 2; ++rg) {
                int kk = kw * 64 + kt * 16 + rg * 8 + kc;
                float2 w = *(const float2*)(row + kk);
                __nv_bfloat16 h0 = __float2bfloat16(w.x);
                __nv_bfloat16 h1 = __float2bfloat16(w.y);
                __nv_bfloat16 l0 = __float2bfloat16(w.x - __bfloat162float(h0));
                __nv_bfloat16 l1 = __float2bfloat16(w.y - __bfloat162float(h1));
                Bh[nt][kt][rg] = (uint32_t)__bfloat16_as_ushort(h0)
                               | ((uint32_t)__bfloat16_as_ushort(h1) << 16);
                Bl[nt][kt][rg] = (uint32_t)__bfloat16_as_ushort(l0)
                               | ((uint32_t)__bfloat16_as_ushort(l1) << 16);
            }
        }
    }
}

extern "C" __global__ void __launch_bounds__(NTHR, 1)
netg_mma(const float* __restrict__ X_p, const float* __restrict__ X_f,
         const float* __restrict__ noise,
         const float* __restrict__ Wih_e, const float* __restrict__ Whh_e,
         const float* __restrict__ bih_e, const float* __restrict__ bhh_e,
         const float* __restrict__ Wih_d, const float* __restrict__ Whh_d,
         const float* __restrict__ bih_d, const float* __restrict__ bhh_d,
         const float* __restrict__ Wfc,   const float* __restrict__ bfc,
         float* __restrict__ out)
{
    extern __shared__ char smc[];
    const uint32_t smb = smem_u32(smc);
    const int tid = threadIdx.x, lane = tid & 31, wid = tid >> 5;
    const int bb = blockIdx.x >> 3, ib = blockIdx.x & 7;
    const int nw = wid & 1, kw = wid >> 1;

    float4* wihb_s = (float4*)(smc + WIHB);
    float*  bhh_s  = (float*)(smc + BHHO);
    float*  wfc_s  = (float*)(smc + WFCO);
    unsigned* cnt  = &g_cnt[bb][0];

    // ---- weights into registers / params into SMEM (encoder phase) ----
    uint32_t Bh[6][4][2], Bl[6][4][2];
    stage_Bregs(Whh_e, Bh, Bl, ib, nw, kw, lane);
    if (tid < 96) {
        int g = tid >> 5, c = tid & 31;
        int row = g * HSZ + ib * 32 + c;
        wihb_s[tid] = make_float4(Wih_e[row * 3], Wih_e[row * 3 + 1],
                                  Wih_e[row * 3 + 2], bih_e[row]);
        bhh_s[tid] = bhh_e[row];
        wfc_s[tid] = Wfc[g * HSZ + ib * 32 + c];
    }

    // epilogue mapping: m = tid>>3 (batch local 0..31), iq = tid&7 (4 hid each)
    const int m_e = tid >> 3, iq = tid & 7;
    const int bg = bb * 32 + m_e;

    // zero h buffer 0 (production index 0)
    {
        uint2 z = make_uint2(0u, 0u);
        *(uint2*)(&g_hbf[0][0][bg * HSZ + ib * 32 + iq * 4]) = z;
        *(uint2*)(&g_hbf[1][0][bg * HSZ + ib * 32 + iq * 4]) = z;
    }
    float hprev[4] = {0.f, 0.f, 0.f, 0.f};
    __syncthreads();
    if (tid == 0) arrive(cnt);   // init arrival: buffer 0 published

    // ldmatrix per-lane address bases (m-tiles at rows r0 and r0+16)
    const int lgrp = lane >> 3, lrow = lane & 7;
    const int r0 = ((lgrp & 1) << 3) + lrow;
    const int segoff = lgrp >> 1;
    const uint32_t rbh0 = smb + A_HI + r0 * 512;
    const uint32_t rbh1 = rbh0 + 16 * 512;
    const uint32_t rbl0 = smb + A_LO + r0 * 512;
    const uint32_t rbl1 = rbl0 + 16 * 512;

    for (int t = 0; t < 2 * TSZ; ++t) {
        const bool enc = t < TSZ;
        const int tt = enc ? t : t - TSZ;

        // ---- entry barrier: all 8 producers of this group reached index t ----
        if (tid == 0) wait_ge(cnt, 8u * (unsigned)(t + 1));
        __syncthreads();

        if (t == TSZ) {   // switch to decoder weights
            stage_Bregs(Whh_d, Bh, Bl, ib, nw, kw, lane);
            if (tid < 96) {
                int g = tid >> 5, c = tid & 31;
                int row = g * HSZ + ib * 32 + c;
                wihb_s[tid] = make_float4(Wih_d[row * 3], Wih_d[row * 3 + 1],
                                          Wih_d[row * 3 + 2], bih_d[row]);
                bhh_s[tid] = bhh_d[row];
            }
        }

        // x_t prefetch (latency hides under staging)
        float x0 = 0.f, x1 = 0.f, x2 = 0.f;
        if (enc) {
            const float* xp = X_p + bg * (TSZ * 3) + tt * 3;
            x0 = xp[0]; x1 = xp[1]; x2 = xp[2];
        } else if (tt > 0) {
            const float* xp = X_f + bg * (TSZ * 3) + (tt - 1) * 3;
            x0 = xp[0]; x1 = xp[1]; x2 = xp[2];
        }

        // distributed head reduce: this CTA's 4 batches of decoder step tt-1
        if (t > TSZ && tid < 12) {
            int bl = ib * 4 + tid / 3, d = tid - (tid / 3) * 3;
            float s2 = bfc[d];
            #pragma unroll
            for (int p = 0; p < 8; ++p)
                s2 += g_yp[(t & 1) ^ 1][bb * 8 + p][bl][d];
            out[((bb * 32 + bl) * TSZ + (tt - 1)) * 3 + d] = s2;
        }

        // ---- stage A (split h): 2048 16B-chunks, 8 per thread ----
        {
            const __nv_bfloat16* s_hi = g_hbf[0][t & 1] + bb * 32 * HSZ;
            const __nv_bfloat16* s_lo = g_hbf[1][t & 1] + bb * 32 * HSZ;
            #pragma unroll
            for (int i2 = 0; i2 < 8; ++i2) {
                int idx = tid + i2 * NTHR;
                int p = idx >> 10, rem = idx & 1023;
                int mm = rem >> 5, s = rem & 31;
                const __nv_bfloat16* src = (p ? s_lo : s_hi) + mm * HSZ + s * 8;
                uint4 v = *(const uint4*)src;
                char* db = smc + (p ? A_LO : A_HI);
                *(uint4*)(db + mm * 512 + ((s ^ (mm & 7)) << 4)) = v;
            }
        }
        __syncthreads();

        // ---- tensor-core GEMM: C[m 0..31][n-half nw] partial over K-quarter ----
        float c[2][6][4];
        #pragma unroll
        for (int a = 0; a < 2; ++a)
            #pragma unroll
            for (int b2 = 0; b2 < 6; ++b2)
                #pragma unroll
                for (int d2 = 0; d2 < 4; ++d2) c[a][b2][d2] = 0.f;

        #pragma unroll
        for (int kt = 0; kt < 4; ++kt) {
            int seg = kw * 8 + kt * 2 + segoff;
            uint32_t so = (uint32_t)((seg ^ lrow) << 4);
            uint32_t ah0[4], ah1[4], al0[4], al1[4];
            ldm4(ah0, rbh0 + so);
            ldm4(ah1, rbh1 + so);
            ldm4(al0, rbl0 + so);
            ldm4(al1, rbl1 + so);
            #pragma unroll
            for (int nt = 0; nt < 6; ++nt) {
                mma16816(c[0][nt], ah0, Bh[nt][kt][0], Bh[nt][kt][1]);
                mma16816(c[1][nt], ah1, Bh[nt][kt][0], Bh[nt][kt][1]);
                mma16816(c[0][nt], al0, Bh[nt][kt][0], Bh[nt][kt][1]);
                mma16816(c[1][nt], al1, Bh[nt][kt][0], Bh[nt][kt][1]);
                mma16816(c[0][nt], ah0, Bl[nt][kt][0], Bl[nt][kt][1]);
                mma16816(c[1][nt], ah1, Bl[nt][kt][0], Bl[nt][kt][1]);
            }
        }

        // store K-partials to SMEM: cb[m*404 + kw*100 + n]
        {
            float* cb = (float*)(smc + CBUF);
            int rr = lane >> 2, cc = (lane & 3) * 2;
            #pragma unroll
            for (int mt = 0; mt < 2; ++mt)
                #pragma unroll
                for (int nt = 0; nt < 6; ++nt) {
                    int mm = mt * 16 + rr;
                    int nn = nw * 48 + nt * 8 + cc;
                    float* p0 = cb + mm * 404 + kw * 100 + nn;
                    *(float2*)p0 = make_float2(c[mt][nt][0], c[mt][nt][1]);
                    *(float2*)(p0 + 8 * 404) = make_float2(c[mt][nt][2], c[mt][nt][3]);
                }
        }
        __syncthreads();

        // ---- epilogue: reduce 4 K-partials, gates, h update ----
        const float* cb = (float*)(smc + CBUF) + m_e * 404 + iq * 4;
        float4 sR = *(const float4*)(cb);
        float4 sZ = *(const float4*)(cb + 32);
        float4 sN = *(const float4*)(cb + 64);
        #pragma unroll
        for (int k2 = 1; k2 < 4; ++k2) {
            const float* p = cb + k2 * 100;
            float4 a = *(const float4*)(p);
            float4 b2 = *(const float4*)(p + 32);
            float4 d2 = *(const float4*)(p + 64);
            sR.x += a.x;  sR.y += a.y;  sR.z += a.z;  sR.w += a.w;
            sZ.x += b2.x; sZ.y += b2.y; sZ.z += b2.z; sZ.w += b2.w;
            sN.x += d2.x; sN.y += d2.y; sN.z += d2.z; sN.w += d2.w;
        }
        float sRa[4] = {sR.x, sR.y, sR.z, sR.w};
        float sZa[4] = {sZ.x, sZ.y, sZ.z, sZ.w};
        float sNa[4] = {sN.x, sN.y, sN.z, sN.w};
        float4 bR4 = *(const float4*)(bhh_s + iq * 4);
        float4 bZ4 = *(const float4*)(bhh_s + 32 + iq * 4);
        float4 bN4 = *(const float4*)(bhh_s + 64 + iq * 4);
        float bRa[4] = {bR4.x, bR4.y, bR4.z, bR4.w};
        float bZa[4] = {bZ4.x, bZ4.y, bZ4.z, bZ4.w};
        float bNa[4] = {bN4.x, bN4.y, bN4.z, bN4.w};

        const bool addn = (t == TSZ - 1);
        float h4[4];
        #pragma unroll
        for (int q = 0; q < 4; ++q) {
            int i = iq * 4 + q;
            float4 wR = wihb_s[i], wZ = wihb_s[32 + i], wN = wihb_s[64 + i];
            float xr = wR.w + wR.x * x0 + wR.y * x1 + wR.z * x2;
            float xz = wZ.w + wZ.x * x0 + wZ.y * x1 + wZ.z * x2;
            float xn = wN.w + wN.x * x0 + wN.y * x1 + wN.z * x2;
            float r = sigf(xr + sRa[q] + bRa[q]);
            float z = sigf(xz + sZa[q] + bZa[q]);
            float n = tanhf_(xn + r * (sNa[q] + bNa[q]));
            float h = n + z * (hprev[q] - n);
            if (addn) h += noise[bg * HSZ + ib * 32 + iq * 4 + q];
            hprev[q] = h;
            h4[q] = h;
        }

        // write split h for next step (production index t+1, buf (t+1)&1)
        {
            __nv_bfloat16 h0 = __float2bfloat16(h4[0]);
            __nv_bfloat16 h1 = __float2bfloat16(h4[1]);
            __nv_bfloat16 h2 = __float2bfloat16(h4[2]);
            __nv_bfloat16 h3 = __float2bfloat16(h4[3]);
            __nv_bfloat16 l0 = __float2bfloat16(h4[0] - __bfloat162float(h0));
            __nv_bfloat16 l1 = __float2bfloat16(h4[1] - __bfloat162float(h1));
            __nv_bfloat16 l2 = __float2bfloat16(h4[2] - __bfloat162float(h2));
            __nv_bfloat16 l3 = __float2bfloat16(h4[3] - __bfloat162float(h3));
            uint32_t hiA = (uint32_t)__bfloat16_as_ushort(h0)
                         | ((uint32_t)__bfloat16_as_ushort(h1) << 16);
            uint32_t hiB = (uint32_t)__bfloat16_as_ushort(h2)
                         | ((uint32_t)__bfloat16_as_ushort(h3) << 16);
            uint32_t loA = (uint32_t)__bfloat16_as_ushort(l0)
                         | ((uint32_t)__bfloat16_as_ushort(l1) << 16);
            uint32_t loB = (uint32_t)__bfloat16_as_ushort(l2)
                         | ((uint32_t)__bfloat16_as_ushort(l3) << 16);
            int off = bg * HSZ + ib * 32 + iq * 4;
            *(uint2*)(&g_hbf[0][(t + 1) & 1][off]) = make_uint2(hiA, hiB);
            *(uint2*)(&g_hbf[1][(t + 1) & 1][off]) = make_uint2(loA, loB);
        }

        // fused FC head partial (decoder): reduce over 8 iq lanes
        if (!enc) {
            float4 w0 = *(const float4*)(wfc_s + iq * 4);
            float4 w1 = *(const float4*)(wfc_s + 32 + iq * 4);
            float4 w2 = *(const float4*)(wfc_s + 64 + iq * 4);
            float y0 = h4[0] * w0.x + h4[1] * w0.y + h4[2] * w0.z + h4[3] * w0.w;
            float y1 = h4[0] * w1.x + h4[1] * w1.y + h4[2] * w1.z + h4[3] * w1.w;
            float y2 = h4[0] * w2.x + h4[1] * w2.y + h4[2] * w2.z + h4[3] * w2.w;
            #pragma unroll
            for (int o = 4; o > 0; o >>= 1) {
                y0 += __shfl_xor_sync(0xffffffffu, y0, o);
                y1 += __shfl_xor_sync(0xffffffffu, y1, o);
                y2 += __shfl_xor_sync(0xffffffffu, y2, o);
            }
            if (iq == 0)
                *(float4*)(&g_yp[t & 1][blockIdx.x][m_e][0]) =
                    make_float4(y0, y1, y2, 0.f);
        }

        // publish production index t+1
        __syncthreads();
        if (tid == 0) arrive(cnt);
    }

    // final head reduction for tstep = 255 (partials at t=511, buf par=1)
    if (tid == 0) wait_ge(cnt, 8u * 513u);
    __syncthreads();
    if (tid < 12) {
        int bl = ib * 4 + tid / 3, d = tid - (tid / 3) * 3;
        float s2 = bfc[d];
        #pragma unroll
        for (int p = 0; p < 8; ++p)
            s2 += g_yp[1][bb * 8 + p][bl][d];
        out[((bb * 32 + bl) * TSZ + (TSZ - 1)) * 3 + d] = s2;
    }
    __syncthreads();
    if (tid == 0) arrive(cnt);

    // counter reset for graph replay: ib==0 waits for all final arrivals,
    // then stores 0 (no CTA reads the counter after its last arrival).
    if (ib == 0 && tid == 0) {
        wait_ge(cnt, 8u * 514u);
        asm volatile("st.release.gpu.u32 [%0], %1;" :: "l"(cnt), "r"(0u) : "memory");
    }
}

extern "C" void kernel_launch(void* const* d_in, const int* in_sizes, int n_in,
                              void* d_out, int out_size) {
    const float* X_p   = (const float*)d_in[0];
    const float* X_f   = (const float*)d_in[1];
    const float* noise = (const float*)d_in[2];
    const float* Wih_e = (const float*)d_in[3];
    const float* Whh_e = (const float*)d_in[4];
    const float* bih_e = (const float*)d_in[5];
    const float* bhh_e = (const float*)d_in[6];
    const float* Wih_d = (const float*)d_in[7];
    const float* Whh_d = (const float*)d_in[8];
    const float* bih_d = (const float*)d_in[9];
    const float* bhh_d = (const float*)d_in[10];
    const float* Wfc   = (const float*)d_in[11];
    const float* bfc   = (const float*)d_in[12];
    float* out = (float*)d_out;

    cudaFuncSetAttribute(netg_mma, cudaFuncAttributeMaxDynamicSharedMemorySize,
                         SMEM_BYTES);
    netg_mma<<<NCTA, NTHR, SMEM_BYTES>>>(
        X_p, X_f, noise, Wih_e, Whh_e, bih_e, bhh_e,
        Wih_d, Whh_d, bih_d, bhh_d, Wfc, bfc, out);
}